// round 15
// baseline (speedup 1.0000x reference)
#include <cuda_runtime.h>
#include <math.h>

#define SW    192
#define SHW   (192*192)
#define HPX   188
#define NC    32
#define NB    2
#define EPS_F 1e-8f
#define GXB   6
#define GYB   47
#define NBLK  (GXB*GYB*NB)   // 564

__device__ double       g_part[NBLK];
__device__ unsigned int g_ctr = 0;

// 24 non-center offsets of the 5x5 window
__device__ __constant__ const int DI24[24] = {
    -2,-2,-2,-2,-2, -1,-1,-1,-1,-1, 0,0, 0,0, 1,1,1,1,1, 2,2,2,2,2
};
__device__ __constant__ const int DJ24[24] = {
    -2,-1, 0, 1, 2, -2,-1, 0, 1, 2, -2,-1, 1,2, -2,-1,0,1,2, -2,-1,0,1,2
};

// Replicates XLA EmitExpm1 then "+1.0" (validated rel_err 0.0 in R7-R14):
//   em1 = |x| < 1e-5 ? x + (x*x)*0.5 : exp(x) - 1 ; return em1 + 1
__device__ __forceinline__ float xla_expm1_p1(float x) {
    float em1;
    if (fabsf(x) < 1e-5f) {
        em1 = __fadd_rn(x, __fmul_rn(__fmul_rn(x, x), 0.5f));
    } else {
        float e = (float)exp((double)x);
        em1 = __fsub_rn(e, 1.0f);
    }
    return __fadd_rn(em1, 1.0f);
}

// Compile-time offset tables (host-side constexpr copies for template unroll)
template <int BASE>
__device__ __forceinline__ double do_offsets(const float* __restrict__ sp,
                                             const float* __restrict__ dpp,
                                             const float* __restrict__ center) {
    constexpr int di_t[24] = {
        -2,-2,-2,-2,-2, -1,-1,-1,-1,-1, 0,0, 0,0, 1,1,1,1,1, 2,2,2,2,2
    };
    constexpr int dj_t[24] = {
        -2,-1, 0, 1, 2, -2,-1, 0, 1, 2, -2,-1, 1,2, -2,-1,0,1,2, -2,-1,0,1,2
    };
    double dsum = 0.0;
    #pragma unroll
    for (int k = 0; k < 12; k++) {
        constexpr_helper:;
        const int off = di_t[BASE + k] * SW + dj_t[BASE + k];   // compile-time
        // hot path: contracted FMA, 32 independent loads in flight
        float s = 0.0f;
        #pragma unroll
        for (int ch = 0; ch < NC; ch++) {
            float d = sp[ch * SHW + off] - center[ch];
            s = fmaf(d, d, s);
        }
        // gate: margin 18.5 > exact cutoff 18.02 (expm1f(-x)+1 == 0 beyond);
        // absorbs fma-contraction drift. Fires ~16x per grid.
        if (s < 18.5f) {
            // exact XLA-order recompute (validated)
            float se = 0.0f;
            for (int ch = 0; ch < NC; ch++) {
                float d = __fsub_rn(sp[ch * SHW + off], sp[ch * SHW]);
                se = __fadd_rn(se, __fmul_rn(d, d));
            }
            float sd  = fmaxf(__fsqrt_rn(se), EPS_F);
            float ssq = __fmul_rn(sd, sd);
            float invc = __fdiv_rn(1.0f, __fadd_rn(dpp[0],   1e-6f));
            float invo = __fdiv_rn(1.0f, __fadd_rn(dpp[off], 1e-6f));
            float dd   = fmaxf(fabsf(__fsub_rn(invc, invo)), EPS_F);
            if (dd > EPS_F && sd > EPS_F) {
                float f1 = xla_expm1_p1(-__fdiv_rn(dd, 10.0f));
                float f2 = xla_expm1_p1(-ssq);
                dsum += (double)__fmul_rn(f1, f2);
            }
        }
    }
    return dsum;
}

__global__ __launch_bounds__(256, 4)
void dgp_kernel(const float* __restrict__ sem, const float* __restrict__ depth,
                float* __restrict__ out) {
    const int tx = threadIdx.x, ty = threadIdx.y;   // block (32, 8)
    const int tid  = ty * 32 + tx;
    const int half = ty >> 2;                       // offset half (warp-uniform)
    const int px = blockIdx.x * 32 + tx;            // output position
    const int py = blockIdx.y * 4 + (ty & 3);       // 47*4 = 188 exact
    const int b  = blockIdx.z;
    const bool valid = (px < HPX);                  // py always < 188

    double dsum = 0.0;

    if (valid) {
        const int y = py + 2, x = px + 2;           // center pixel
        const float* __restrict__ sp  = sem + ((size_t)b * NC) * SHW + y * SW + x;
        const float* __restrict__ dpp = depth + b * SHW + y * SW + x;

        // cache center's 32 channels (coalesced: warp spans 32 consecutive x)
        float center[NC];
        #pragma unroll
        for (int ch = 0; ch < NC; ch++) center[ch] = sp[ch * SHW];

        if (half == 0) dsum = do_offsets<0>(sp, dpp, center);
        else           dsum = do_offsets<12>(sp, dpp, center);
    }

    // ---- block reduction -> per-block slot (no hot-path barriers) ----
    const int wid = tid >> 5, lne = tid & 31;
    #pragma unroll
    for (int o = 16; o > 0; o >>= 1)
        dsum += __shfl_down_sync(0xffffffffu, dsum, o);

    __shared__ double ws[8];
    __shared__ bool   is_last;
    if (lne == 0) ws[wid] = dsum;
    __syncthreads();

    const int bid = (blockIdx.z * GYB + blockIdx.y) * GXB + blockIdx.x;
    if (tid == 0) {
        double t = 0.0;
        #pragma unroll
        for (int w = 0; w < 8; w++) t += ws[w];
        g_part[bid] = t;
        __threadfence();
        unsigned old = atomicAdd(&g_ctr, 1u);
        is_last = (old == NBLK - 1);
    }
    __syncthreads();

    // ---- last block finalizes (single launch total) ----
    if (is_last) {
        double v = 0.0;
        for (int i = tid; i < NBLK; i += 256) v += g_part[i];
        #pragma unroll
        for (int o = 16; o > 0; o >>= 1)
            v += __shfl_down_sync(0xffffffffu, v, o);
        __shared__ double fs[8];
        if (lne == 0) fs[wid] = v;
        __syncthreads();
        if (tid == 0) {
            double s = 0.0;
            #pragma unroll
            for (int w = 0; w < 8; w++) s += fs[w];
            // mean over (B,B,k,k,P): S / (25*B*P) = S / 1,767,200
            out[0] = (float)(s / 1767200.0);
            g_ctr  = 0;          // reset for next graph replay
        }
    }
}

extern "C" void kernel_launch(void* const* d_in, const int* in_sizes, int n_in,
                              void* d_out, int out_size) {
    const float* sem   = (const float*)d_in[0];  // (2, 32, 192, 192) f32
    const float* depth = (const float*)d_in[1];  // (2, 1, 192, 192) f32

    dim3 blk(32, 8);
    dim3 grd(GXB, GYB, NB);
    dgp_kernel<<<grd, blk>>>(sem, depth, (float*)d_out);
}

// round 16
// speedup vs baseline: 1.2490x; 1.2490x over previous
#include <cuda_runtime.h>
#include <math.h>

#define SW    192
#define SHW   (192*192)
#define HPX   188
#define NC    32
#define NB    2
#define EPS_F 1e-8f
#define GXB   6
#define GYB   24
#define NBLK  (GXB*GYB*NB)   // 288

__device__ double       g_part[NBLK];
__device__ unsigned int g_ctr = 0;

// Replicates XLA EmitExpm1 then "+1.0" (validated rel_err 0.0 in R7-R15):
//   em1 = |x| < 1e-5 ? x + (x*x)*0.5 : exp(x) - 1 ; return em1 + 1
__device__ __forceinline__ float xla_expm1_p1(float x) {
    float em1;
    if (fabsf(x) < 1e-5f) {
        em1 = __fadd_rn(x, __fmul_rn(__fmul_rn(x, x), 0.5f));
    } else {
        float e = (float)exp((double)x);
        em1 = __fsub_rn(e, 1.0f);
    }
    return __fadd_rn(em1, 1.0f);
}

__global__ __launch_bounds__(256)
void dgp_kernel(const float* __restrict__ sem, const float* __restrict__ depth,
                float* __restrict__ out) {
    const int tx = threadIdx.x, ty = threadIdx.y;   // block (32, 8)
    const int tid = ty * 32 + tx;
    const int px = blockIdx.x * 32 + tx;            // output position
    const int py = blockIdx.y * 8 + ty;
    const int b  = blockIdx.z;
    const bool valid = (px < HPX) && (py < HPX);

    double dsum = 0.0;

    if (valid) {
        const int y = py + 2, x = px + 2;           // center pixel
        const float* __restrict__ sp = sem + ((size_t)b * NC) * SHW + y * SW + x;

        // cache center's 32 channels in registers (coalesced: warp spans 32 consecutive x)
        float center[NC];
        #pragma unroll
        for (int ch = 0; ch < NC; ch++) center[ch] = sp[ch * SHW];

        #pragma unroll
        for (int di = -2; di <= 2; di++) {
            #pragma unroll
            for (int dj = -2; dj <= 2; dj++) {
                if (di == 0 && dj == 0) continue;   // center_mask
                const int off = di * SW + dj;
                // hot path: 4 independent FMA chains (8 deep each) -> 4x ILP on the
                // accumulate; loads stay batched (MLP ~32).
                float s0 = 0.0f, s1 = 0.0f, s2 = 0.0f, s3 = 0.0f;
                #pragma unroll
                for (int ch = 0; ch < NC; ch += 4) {
                    float d0 = sp[(ch + 0) * SHW + off] - center[ch + 0];
                    float d1 = sp[(ch + 1) * SHW + off] - center[ch + 1];
                    float d2 = sp[(ch + 2) * SHW + off] - center[ch + 2];
                    float d3 = sp[(ch + 3) * SHW + off] - center[ch + 3];
                    s0 = fmaf(d0, d0, s0);
                    s1 = fmaf(d1, d1, s1);
                    s2 = fmaf(d2, d2, s2);
                    s3 = fmaf(d3, d3, s3);
                }
                float s = (s0 + s1) + (s2 + s3);
                // gate: margin 18.5 > exact cutoff 18.02 (expm1f(-x)+1 == 0 beyond);
                // absorbs contraction + reassociation drift. Fires ~16x per grid.
                if (s < 18.5f) {
                    // exact XLA-order recompute (validated)
                    float se = 0.0f;
                    for (int ch = 0; ch < NC; ch++) {
                        float d = __fsub_rn(sp[ch * SHW + off], sp[ch * SHW]);
                        se = __fadd_rn(se, __fmul_rn(d, d));
                    }
                    float sd  = fmaxf(__fsqrt_rn(se), EPS_F);
                    float ssq = __fmul_rn(sd, sd);
                    const float* __restrict__ dpp = depth + b * SHW + y * SW + x;
                    float invc = __fdiv_rn(1.0f, __fadd_rn(dpp[0],   1e-6f));
                    float invo = __fdiv_rn(1.0f, __fadd_rn(dpp[off], 1e-6f));
                    float dd   = fmaxf(fabsf(__fsub_rn(invc, invo)), EPS_F);
                    if (dd > EPS_F && sd > EPS_F) {
                        float f1 = xla_expm1_p1(-__fdiv_rn(dd, 10.0f));
                        float f2 = xla_expm1_p1(-ssq);
                        dsum += (double)__fmul_rn(f1, f2);
                    }
                }
            }
        }
    }

    // ---- block reduction -> per-block slot (no hot-path barriers) ----
    const int wid = tid >> 5, lne = tid & 31;
    #pragma unroll
    for (int o = 16; o > 0; o >>= 1)
        dsum += __shfl_down_sync(0xffffffffu, dsum, o);

    __shared__ double ws[8];
    __shared__ bool   is_last;
    if (lne == 0) ws[wid] = dsum;
    __syncthreads();

    const int bid = (blockIdx.z * GYB + blockIdx.y) * GXB + blockIdx.x;
    if (tid == 0) {
        double t = 0.0;
        #pragma unroll
        for (int w = 0; w < 8; w++) t += ws[w];
        g_part[bid] = t;
        __threadfence();
        unsigned old = atomicAdd(&g_ctr, 1u);
        is_last = (old == NBLK - 1);
    }
    __syncthreads();

    // ---- last block finalizes (single launch total) ----
    if (is_last) {
        double v = 0.0;
        for (int i = tid; i < NBLK; i += 256) v += g_part[i];
        #pragma unroll
        for (int o = 16; o > 0; o >>= 1)
            v += __shfl_down_sync(0xffffffffu, v, o);
        __shared__ double fs[8];
        if (lne == 0) fs[wid] = v;
        __syncthreads();
        if (tid == 0) {
            double s = 0.0;
            #pragma unroll
            for (int w = 0; w < 8; w++) s += fs[w];
            // mean over (B,B,k,k,P): S / (25*B*P) = S / 1,767,200
            out[0] = (float)(s / 1767200.0);
            g_ctr  = 0;          // reset for next graph replay
        }
    }
}

extern "C" void kernel_launch(void* const* d_in, const int* in_sizes, int n_in,
                              void* d_out, int out_size) {
    const float* sem   = (const float*)d_in[0];  // (2, 32, 192, 192) f32
    const float* depth = (const float*)d_in[1];  // (2, 1, 192, 192) f32

    dim3 blk(32, 8);
    dim3 grd(GXB, GYB, NB);
    dgp_kernel<<<grd, blk>>>(sem, depth, (float*)d_out);
}